// round 16
// baseline (speedup 1.0000x reference)
#include <cuda_runtime.h>
#include <cuda_bf16.h>
#include <cuda_fp16.h>
#include <cstdint>
#include <cstddef>

// ---------------- problem dims (fixed) ----------------
#define DIM_B 4096
#define DIM_N 16384
#define DIM_D 1024
#define SPLITK 8

// ---------------- device scratch (static; no allocation allowed) ----------------
__device__ __half         g_x_hi [DIM_B * DIM_D];
__device__ __half         g_x_lo [DIM_B * DIM_D];
__device__ __half         g_ci_hi[DIM_N * DIM_D];
__device__ __half         g_ctT_hi[(size_t)DIM_D * DIM_N];  // cache_text^T (fp16)
__device__ float          g_S   [(size_t)DIM_B * DIM_N];    // logits, 256 MB
__device__ __half         g_w_hi[(size_t)DIM_B * DIM_N];    // softmax weights (fp16 split)
__device__ __half         g_w_lo[(size_t)DIM_B * DIM_N];
__device__ float          g_R   [SPLITK][(size_t)DIM_B * DIM_D]; // split-K partials

// ---------------- PTX helpers (portable: sm_80+ instructions only) ----------------
__device__ __forceinline__ uint32_t smem_u32(const void* p) {
    uint32_t a;
    asm("{ .reg .u64 t; cvta.to.shared.u64 t, %1; cvt.u32.u64 %0, t; }" : "=r"(a) : "l"(p));
    return a;
}
__device__ __forceinline__ void cp16(uint32_t saddr, const void* g) {
    asm volatile("cp.async.cg.shared.global [%0], [%1], 16;" :: "r"(saddr), "l"(g) : "memory");
}
__device__ __forceinline__ void cp_commit() {
    asm volatile("cp.async.commit_group;" ::: "memory");
}
template <int N>
__device__ __forceinline__ void cp_wait() {
    asm volatile("cp.async.wait_group %0;" :: "n"(N) : "memory");
}
__device__ __forceinline__ void ldsm_x4(uint32_t* r, uint32_t addr) {
    asm volatile("ldmatrix.sync.aligned.m8n8.x4.shared.b16 {%0,%1,%2,%3}, [%4];"
                 : "=r"(r[0]), "=r"(r[1]), "=r"(r[2]), "=r"(r[3]) : "r"(addr));
}
__device__ __forceinline__ void ldsm_x2(uint32_t* r, uint32_t addr) {
    asm volatile("ldmatrix.sync.aligned.m8n8.x2.shared.b16 {%0,%1}, [%2];"
                 : "=r"(r[0]), "=r"(r[1]) : "r"(addr));
}
__device__ __forceinline__ void mma_f32acc(float* d, const uint32_t* a, const uint32_t* b) {
    asm volatile("mma.sync.aligned.m16n8k16.row.col.f32.f16.f16.f32 "
                 "{%0,%1,%2,%3}, {%4,%5,%6,%7}, {%8,%9}, {%0,%1,%2,%3};"
                 : "+f"(d[0]), "+f"(d[1]), "+f"(d[2]), "+f"(d[3])
                 : "r"(a[0]), "r"(a[1]), "r"(a[2]), "r"(a[3]), "r"(b[0]), "r"(b[1]));
}

// ---------------- split helpers ----------------
__device__ __forceinline__ uint32_t pack_h(__half a, __half b) {
    __half2 t(a, b);
    return *reinterpret_cast<uint32_t*>(&t);
}
__device__ __forceinline__ void split1h(float v, __half& h, __half& l) {
    h = __float2half_rn(v);
    l = __float2half_rn(v - __half2float(h));
}

// ---------------- kernel: elementwise fp32 -> fp16 hi/lo ----------------
__global__ void split_h_kernel(const float4* __restrict__ in, uint2* __restrict__ hi,
                               uint2* __restrict__ lo, int n4) {
    int i = blockIdx.x * blockDim.x + threadIdx.x;
    if (i >= n4) return;
    float4 v = in[i];
    __half h0, h1, h2, h3, l0, l1, l2, l3;
    split1h(v.x, h0, l0); split1h(v.y, h1, l1); split1h(v.z, h2, l2); split1h(v.w, h3, l3);
    hi[i] = make_uint2(pack_h(h0, h1), pack_h(h2, h3));
    lo[i] = make_uint2(pack_h(l0, l1), pack_h(l2, l3));
}

// ---------------- kernel: elementwise fp32 -> fp16 (hi only) ----------------
__global__ void cvt_h_kernel(const float4* __restrict__ in, uint2* __restrict__ hi, int n4) {
    int i = blockIdx.x * blockDim.x + threadIdx.x;
    if (i >= n4) return;
    float4 v = in[i];
    hi[i] = make_uint2(pack_h(__float2half_rn(v.x), __float2half_rn(v.y)),
                       pack_h(__float2half_rn(v.z), __float2half_rn(v.w)));
}

// ---------------- kernel: transpose + fp16 convert (ct [N,D] -> ctT [D,N]) ----------------
__global__ void transpose_h_kernel(const float* __restrict__ in,
                                   __half* __restrict__ hi) {
    __shared__ float tile[32][33];
    int n0 = blockIdx.y * 32;
    int d0 = blockIdx.x * 32;
    int tx = threadIdx.x, ty = threadIdx.y;
    #pragma unroll
    for (int j = 0; j < 32; j += 8)
        tile[ty + j][tx] = in[(size_t)(n0 + ty + j) * DIM_D + d0 + tx];
    __syncthreads();
    #pragma unroll
    for (int j = 0; j < 32; j += 8) {
        float v = tile[tx][ty + j];
        size_t o = (size_t)(d0 + ty + j) * DIM_N + n0 + tx;
        hi[o] = __float2half_rn(v);
    }
}

// ---------------- kernel: row softmax over 16384 + split to fp16 hi/lo ----------------
__global__ void softmax_split_kernel(const float* __restrict__ S,
                                     const float* __restrict__ beta_p,
                                     uint2* __restrict__ whi, uint2* __restrict__ wlo) {
    __shared__ float red[16];
    __shared__ float bcast;
    int row = blockIdx.x, t = threadIdx.x;
    int lane = t & 31, wid = t >> 5;
    const float4* src = reinterpret_cast<const float4*>(S + (size_t)row * DIM_N);
    float beta = *beta_p;
    float4 v[8];
    float mx = -3.4e38f;
    #pragma unroll
    for (int j = 0; j < 8; j++) {
        float4 a = src[j * 512 + t];
        a.x *= beta; a.y *= beta; a.z *= beta; a.w *= beta;
        v[j] = a;
        mx = fmaxf(mx, fmaxf(fmaxf(a.x, a.y), fmaxf(a.z, a.w)));
    }
    #pragma unroll
    for (int o = 16; o > 0; o >>= 1) mx = fmaxf(mx, __shfl_xor_sync(0xffffffffu, mx, o));
    if (lane == 0) red[wid] = mx;
    __syncthreads();
    if (t == 0) {
        float m = red[0];
        #pragma unroll
        for (int i = 1; i < 16; i++) m = fmaxf(m, red[i]);
        bcast = m;
    }
    __syncthreads();
    mx = bcast;
    float s = 0.f;
    #pragma unroll
    for (int j = 0; j < 8; j++) {
        v[j].x = __expf(v[j].x - mx);
        v[j].y = __expf(v[j].y - mx);
        v[j].z = __expf(v[j].z - mx);
        v[j].w = __expf(v[j].w - mx);
        s += v[j].x + v[j].y + v[j].z + v[j].w;
    }
    #pragma unroll
    for (int o = 16; o > 0; o >>= 1) s += __shfl_xor_sync(0xffffffffu, s, o);
    if (lane == 0) red[wid] = s;
    __syncthreads();
    if (t == 0) {
        float m = 0.f;
        #pragma unroll
        for (int i = 0; i < 16; i++) m += red[i];
        bcast = m;
    }
    __syncthreads();
    float inv = 1.0f / bcast;
    size_t ob = (size_t)row * (DIM_N / 4);
    #pragma unroll
    for (int j = 0; j < 8; j++) {
        float w0 = v[j].x * inv, w1 = v[j].y * inv, w2 = v[j].z * inv, w3 = v[j].w * inv;
        __half h0, h1, h2, h3, l0, l1, l2, l3;
        split1h(w0, h0, l0); split1h(w1, h1, l1); split1h(w2, h2, l2); split1h(w3, h3, l3);
        whi[ob + j * 512 + t] = make_uint2(pack_h(h0, h1), pack_h(h2, h3));
        wlo[ob + j * 512 + t] = make_uint2(pack_h(l0, l1), pack_h(l2, l3));
    }
}

// ---------------- split-precision GEMM via mma.sync ----------------
// C[M,Ntot] (fp32) = (Ah+Al)[M,K] . Bh[Ntot,K]^T   (2 products, fp16, fp32 acc)
// tile 128x128, BK=64, 2-stage cp.async pipeline, 256 threads, warp grid 4(M)x2(N),
// 2 CTAs per SM (cross-CTA overlap fills per-chunk sync/wait bubbles).
#define G_THREADS   256
#define TILE_BYTES  16384                   // 128 rows x 64 halfwords (128 B/row)
#define STAGE_BYTES (3 * TILE_BYTES)        // Ah, Al, Bh = 49152
#define GEMM_SMEM   (2 * STAGE_BYTES)       // 98304 -> 2 CTAs/SM

__global__ void __launch_bounds__(G_THREADS, 2)
gemm_split_kernel(const uint16_t* __restrict__ Ah, const uint16_t* __restrict__ Al,
                  const uint16_t* __restrict__ Bh,
                  float* __restrict__ C,
                  int M, int Ntot, int ldk, int Kloc, int group_m) {
    constexpr int NWM = 4, NWN = 2;
    constexpr int MI = 128 / NWM / 16;      // 2 m16 tiles per warp
    constexpr int NJ = 128 / NWN / 8;       // 8 n8 tiles per warp

    extern __shared__ char smem[];
    uint32_t sbase = smem_u32(smem);
    const int tid = threadIdx.x, lane = tid & 31, warp = tid >> 5;
    const int wm = warp % NWM, wn = warp / NWM;

    // supertile rasterization for L2 reuse
    int num_pid_m = M >> 7, num_pid_n = Ntot >> 7;
    int pid = blockIdx.x;
    int per_grp = group_m * num_pid_n;
    int gid = pid / per_grp;
    int first_m = gid * group_m;
    int gsm = num_pid_m - first_m; if (gsm > group_m) gsm = group_m;
    int pid_m = first_m + (pid % gsm);
    int pid_n = (pid % per_grp) / gsm;
    const int m0 = pid_m << 7, n0 = pid_n << 7;

    const int kbeg = blockIdx.y * Kloc;
    C += (size_t)blockIdx.y * M * Ntot;

    const uint16_t* srcs[3] = {Ah, Al, Bh};
    const int rows0[3] = {m0, m0, n0};

    auto stage_load = [&](int c, int buf) {
        size_t k0 = (size_t)kbeg + (size_t)c * 64;
        uint32_t sb = sbase + buf * STAGE_BYTES;
        #pragma unroll
        for (int t = 0; t < 3; t++) {
            const uint16_t* src = srcs[t];
            int r0 = rows0[t];
            #pragma unroll
            for (int i = 0; i < 4; i++) {
                int idx = tid + i * G_THREADS;          // 0..1023
                int r = idx >> 3, cc = idx & 7;
                const void* g = src + (size_t)(r0 + r) * ldk + k0 + cc * 8;
                uint32_t off = (uint32_t)(r * 128 + (cc * 16 ^ ((r & 7) << 4)));
                cp16(sb + t * TILE_BYTES + off, g);
            }
        }
        cp_commit();
    };

    float acc[MI][NJ][4];
    #pragma unroll
    for (int i = 0; i < MI; i++)
        #pragma unroll
        for (int j = 0; j < NJ; j++)
            #pragma unroll
            for (int q = 0; q < 4; q++) acc[i][j][q] = 0.f;

    const int nch = Kloc >> 6;   // BK = 64
    stage_load(0, 0);

    // per-lane ldmatrix address components (row stride 128 B)
    const int rowA = wm * 32 + (lane & 7) + ((lane >> 3) & 1) * 8;    // + i*16
    const int kbA  = (lane >> 4) * 16;                                // bytes
    const uint32_t xorA = (uint32_t)((rowA & 7) << 4);
    const int rowB = wn * 64 + (lane & 7);                            // + j*8
    const int kbB  = ((lane >> 3) & 1) * 16;                          // bytes
    const uint32_t xorB = (uint32_t)((rowB & 7) << 4);

    for (int c = 0; c < nch; ++c) {
        if (c + 1 < nch) {
            stage_load(c + 1, (c + 1) & 1);
            cp_wait<1>();
        } else {
            cp_wait<0>();
        }
        __syncthreads();

        uint32_t sA  = sbase + (c & 1) * STAGE_BYTES;
        uint32_t sAl = sA + TILE_BYTES;
        uint32_t sBh = sA + 2 * TILE_BYTES;

        #pragma unroll
        for (int ks = 0; ks < 4; ks++) {
            uint32_t ah[MI][4], al[MI][4], bh[NJ][2];
            #pragma unroll
            for (int i = 0; i < MI; i++) {
                uint32_t off = (uint32_t)((rowA + i * 16) * 128) + ((uint32_t)(ks * 32 + kbA) ^ xorA);
                ldsm_x4(ah[i], sA  + off);
                ldsm_x4(al[i], sAl + off);
            }
            #pragma unroll
            for (int j = 0; j < NJ; j++) {
                uint32_t off = (uint32_t)((rowB + j * 8) * 128) + ((uint32_t)(ks * 32 + kbB) ^ xorB);
                ldsm_x2(bh[j], sBh + off);
            }
            // product-major: main then correction (same K order -> stable numerics)
            #pragma unroll
            for (int i = 0; i < MI; i++)
                #pragma unroll
                for (int j = 0; j < NJ; j++)
                    mma_f32acc(acc[i][j], ah[i], bh[j]);
            #pragma unroll
            for (int i = 0; i < MI; i++)
                #pragma unroll
                for (int j = 0; j < NJ; j++)
                    mma_f32acc(acc[i][j], al[i], bh[j]);
        }
        __syncthreads();
    }

    // epilogue: direct fp32 stores
    const int r0 = m0 + wm * 32 + (lane >> 2);
    const int c0 = n0 + wn * 64 + (lane & 3) * 2;
    #pragma unroll
    for (int i = 0; i < MI; i++) {
        #pragma unroll
        for (int j = 0; j < NJ; j++) {
            int r = r0 + i * 16, cc = c0 + j * 8;
            float2 v01 = make_float2(acc[i][j][0], acc[i][j][1]);
            float2 v23 = make_float2(acc[i][j][2], acc[i][j][3]);
            *reinterpret_cast<float2*>(&C[(size_t)r * Ntot + cc])       = v01;
            *reinterpret_cast<float2*>(&C[(size_t)(r + 8) * Ntot + cc]) = v23;
        }
    }
}

// ---------------- combine: out = x + alpha * sum_{s<8} R_s ----------------
__global__ void combine_kernel(const float4* __restrict__ x,
                               const float4* __restrict__ R,   // 8 contiguous partials
                               const float* __restrict__ alpha_p,
                               float4* __restrict__ out, int n4) {
    int i = blockIdx.x * blockDim.x + threadIdx.x;
    if (i >= n4) return;
    float al = *alpha_p;
    float4 xv = x[i];
    float sx = 0.f, sy = 0.f, sz = 0.f, sw = 0.f;
    #pragma unroll
    for (int s = 0; s < SPLITK; s++) {
        float4 r = R[(size_t)s * n4 + i];
        sx += r.x; sy += r.y; sz += r.z; sw += r.w;
    }
    float4 o;
    o.x = xv.x + al * sx;
    o.y = xv.y + al * sy;
    o.z = xv.z + al * sz;
    o.w = xv.w + al * sw;
    out[i] = o;
}

// ---------------- launch ----------------
extern "C" void kernel_launch(void* const* d_in, const int* in_sizes, int n_in,
                              void* d_out, int out_size) {
    const float* x     = (const float*)d_in[0];
    const float* ci    = (const float*)d_in[1];
    const float* ct    = (const float*)d_in[2];
    const float* beta  = (const float*)d_in[3];
    const float* alpha = (const float*)d_in[4];
    float* out = (float*)d_out;

    void *xh, *xl, *cih, *cth, *Sp, *wh, *wl, *Rp;
    cudaGetSymbolAddress(&xh,  g_x_hi);
    cudaGetSymbolAddress(&xl,  g_x_lo);
    cudaGetSymbolAddress(&cih, g_ci_hi);
    cudaGetSymbolAddress(&cth, g_ctT_hi);
    cudaGetSymbolAddress(&Sp,  g_S);
    cudaGetSymbolAddress(&wh,  g_w_hi);
    cudaGetSymbolAddress(&wl,  g_w_lo);
    cudaGetSymbolAddress(&Rp,  g_R);

    cudaFuncSetAttribute(gemm_split_kernel,
                         cudaFuncAttributeMaxDynamicSharedMemorySize, GEMM_SMEM);

    // 1) split x to fp16 hi/lo; convert ci to fp16; transpose + fp16 convert ct
    {
        int n4 = DIM_B * DIM_D / 4;
        split_h_kernel<<<n4 / 256, 256>>>((const float4*)x, (uint2*)xh, (uint2*)xl, n4);
    }
    {
        int n4 = DIM_N * DIM_D / 4;
        cvt_h_kernel<<<n4 / 256, 256>>>((const float4*)ci, (uint2*)cih, n4);
    }
    transpose_h_kernel<<<dim3(DIM_D / 32, DIM_N / 32), dim3(32, 8)>>>(ct, (__half*)cth);

    // 2) logits S = x . ci^T   [4096 x 16384], K = 1024  (fp16, 2-product)
    gemm_split_kernel<<<dim3((DIM_B / 128) * (DIM_N / 128), 1), G_THREADS, GEMM_SMEM>>>(
        (const uint16_t*)xh, (const uint16_t*)xl, (const uint16_t*)cih,
        (float*)Sp, DIM_B, DIM_N, DIM_D, DIM_D, 8);

    // 3) softmax(beta * S) row-wise -> fp16 hi/lo weights
    softmax_split_kernel<<<DIM_B, 512>>>((const float*)Sp, beta, (uint2*)wh, (uint2*)wl);

    // 4) R_s = W . ctT^T over K-slice s  [4096 x 1024], K = 16384, split-K = 8
    //    (fp16, 2-product: (Wh+Wl) . Vh)  -> 2048 CTAs = ~6.9 waves at 2 CTA/SM
    gemm_split_kernel<<<dim3((DIM_B / 128) * (DIM_D / 128), SPLITK), G_THREADS, GEMM_SMEM>>>(
        (const uint16_t*)wh, (const uint16_t*)wl, (const uint16_t*)cth,
        (float*)Rp, DIM_B, DIM_D, DIM_N, DIM_N / SPLITK, 4);

    // 5) out = x + alpha * sum_s R_s
    {
        int n4 = DIM_B * DIM_D / 4;
        combine_kernel<<<n4 / 256, 256>>>(
            (const float4*)x, (const float4*)Rp, alpha, (float4*)out, n4);
    }
}

// round 17
// speedup vs baseline: 1.2735x; 1.2735x over previous
#include <cuda_runtime.h>
#include <cuda_bf16.h>
#include <cuda_fp16.h>
#include <cstdint>
#include <cstddef>

// ---------------- problem dims (fixed) ----------------
#define DIM_B 4096
#define DIM_N 16384
#define DIM_D 1024
#define SPLITK 4

// ---------------- device scratch (static; no allocation allowed) ----------------
__device__ __half         g_x_hi [DIM_B * DIM_D];
__device__ __half         g_x_lo [DIM_B * DIM_D];
__device__ __half         g_ci_hi[DIM_N * DIM_D];
__device__ __half         g_ctT_hi[(size_t)DIM_D * DIM_N];  // cache_text^T (fp16)
__device__ float          g_S   [(size_t)DIM_B * DIM_N];    // logits, 256 MB
__device__ __half         g_w_hi[(size_t)DIM_B * DIM_N];    // softmax weights (fp16)
__device__ float          g_R   [SPLITK][(size_t)DIM_B * DIM_D]; // split-K partials

// ---------------- PTX helpers (portable: sm_80+ instructions only) ----------------
__device__ __forceinline__ uint32_t smem_u32(const void* p) {
    uint32_t a;
    asm("{ .reg .u64 t; cvta.to.shared.u64 t, %1; cvt.u32.u64 %0, t; }" : "=r"(a) : "l"(p));
    return a;
}
__device__ __forceinline__ void cp16(uint32_t saddr, const void* g) {
    asm volatile("cp.async.cg.shared.global [%0], [%1], 16;" :: "r"(saddr), "l"(g) : "memory");
}
__device__ __forceinline__ void cp_commit() {
    asm volatile("cp.async.commit_group;" ::: "memory");
}
template <int N>
__device__ __forceinline__ void cp_wait() {
    asm volatile("cp.async.wait_group %0;" :: "n"(N) : "memory");
}
__device__ __forceinline__ void ldsm_x4(uint32_t* r, uint32_t addr) {
    asm volatile("ldmatrix.sync.aligned.m8n8.x4.shared.b16 {%0,%1,%2,%3}, [%4];"
                 : "=r"(r[0]), "=r"(r[1]), "=r"(r[2]), "=r"(r[3]) : "r"(addr));
}
__device__ __forceinline__ void ldsm_x2(uint32_t* r, uint32_t addr) {
    asm volatile("ldmatrix.sync.aligned.m8n8.x2.shared.b16 {%0,%1}, [%2];"
                 : "=r"(r[0]), "=r"(r[1]) : "r"(addr));
}
__device__ __forceinline__ void mma_f32acc(float* d, const uint32_t* a, const uint32_t* b) {
    asm volatile("mma.sync.aligned.m16n8k16.row.col.f32.f16.f16.f32 "
                 "{%0,%1,%2,%3}, {%4,%5,%6,%7}, {%8,%9}, {%0,%1,%2,%3};"
                 : "+f"(d[0]), "+f"(d[1]), "+f"(d[2]), "+f"(d[3])
                 : "r"(a[0]), "r"(a[1]), "r"(a[2]), "r"(a[3]), "r"(b[0]), "r"(b[1]));
}

// ---------------- split helpers ----------------
__device__ __forceinline__ uint32_t pack_h(__half a, __half b) {
    __half2 t(a, b);
    return *reinterpret_cast<uint32_t*>(&t);
}
__device__ __forceinline__ void split1h(float v, __half& h, __half& l) {
    h = __float2half_rn(v);
    l = __float2half_rn(v - __half2float(h));
}

// ---------------- kernel: elementwise fp32 -> fp16 hi/lo ----------------
__global__ void split_h_kernel(const float4* __restrict__ in, uint2* __restrict__ hi,
                               uint2* __restrict__ lo, int n4) {
    int i = blockIdx.x * blockDim.x + threadIdx.x;
    if (i >= n4) return;
    float4 v = in[i];
    __half h0, h1, h2, h3, l0, l1, l2, l3;
    split1h(v.x, h0, l0); split1h(v.y, h1, l1); split1h(v.z, h2, l2); split1h(v.w, h3, l3);
    hi[i] = make_uint2(pack_h(h0, h1), pack_h(h2, h3));
    lo[i] = make_uint2(pack_h(l0, l1), pack_h(l2, l3));
}

// ---------------- kernel: elementwise fp32 -> fp16 (hi only) ----------------
__global__ void cvt_h_kernel(const float4* __restrict__ in, uint2* __restrict__ hi, int n4) {
    int i = blockIdx.x * blockDim.x + threadIdx.x;
    if (i >= n4) return;
    float4 v = in[i];
    hi[i] = make_uint2(pack_h(__float2half_rn(v.x), __float2half_rn(v.y)),
                       pack_h(__float2half_rn(v.z), __float2half_rn(v.w)));
}

// ---------------- kernel: transpose + fp16 convert (ct [N,D] -> ctT [D,N]) ----------------
__global__ void transpose_h_kernel(const float* __restrict__ in,
                                   __half* __restrict__ hi) {
    __shared__ float tile[32][33];
    int n0 = blockIdx.y * 32;
    int d0 = blockIdx.x * 32;
    int tx = threadIdx.x, ty = threadIdx.y;
    #pragma unroll
    for (int j = 0; j < 32; j += 8)
        tile[ty + j][tx] = in[(size_t)(n0 + ty + j) * DIM_D + d0 + tx];
    __syncthreads();
    #pragma unroll
    for (int j = 0; j < 32; j += 8) {
        float v = tile[tx][ty + j];
        size_t o = (size_t)(d0 + ty + j) * DIM_N + n0 + tx;
        hi[o] = __float2half_rn(v);
    }
}

// ---------------- kernel: row softmax over 16384 -> fp16 weights (hi only) ----------------
__global__ void softmax_h_kernel(const float* __restrict__ S,
                                 const float* __restrict__ beta_p,
                                 uint2* __restrict__ whi) {
    __shared__ float red[16];
    __shared__ float bcast;
    int row = blockIdx.x, t = threadIdx.x;
    int lane = t & 31, wid = t >> 5;
    const float4* src = reinterpret_cast<const float4*>(S + (size_t)row * DIM_N);
    float beta = *beta_p;
    float4 v[8];
    float mx = -3.4e38f;
    #pragma unroll
    for (int j = 0; j < 8; j++) {
        float4 a = src[j * 512 + t];
        a.x *= beta; a.y *= beta; a.z *= beta; a.w *= beta;
        v[j] = a;
        mx = fmaxf(mx, fmaxf(fmaxf(a.x, a.y), fmaxf(a.z, a.w)));
    }
    #pragma unroll
    for (int o = 16; o > 0; o >>= 1) mx = fmaxf(mx, __shfl_xor_sync(0xffffffffu, mx, o));
    if (lane == 0) red[wid] = mx;
    __syncthreads();
    if (t == 0) {
        float m = red[0];
        #pragma unroll
        for (int i = 1; i < 16; i++) m = fmaxf(m, red[i]);
        bcast = m;
    }
    __syncthreads();
    mx = bcast;
    float s = 0.f;
    #pragma unroll
    for (int j = 0; j < 8; j++) {
        v[j].x = __expf(v[j].x - mx);
        v[j].y = __expf(v[j].y - mx);
        v[j].z = __expf(v[j].z - mx);
        v[j].w = __expf(v[j].w - mx);
        s += v[j].x + v[j].y + v[j].z + v[j].w;
    }
    #pragma unroll
    for (int o = 16; o > 0; o >>= 1) s += __shfl_xor_sync(0xffffffffu, s, o);
    if (lane == 0) red[wid] = s;
    __syncthreads();
    if (t == 0) {
        float m = 0.f;
        #pragma unroll
        for (int i = 0; i < 16; i++) m += red[i];
        bcast = m;
    }
    __syncthreads();
    float inv = 1.0f / bcast;
    size_t ob = (size_t)row * (DIM_N / 4);
    #pragma unroll
    for (int j = 0; j < 8; j++) {
        float w0 = v[j].x * inv, w1 = v[j].y * inv, w2 = v[j].z * inv, w3 = v[j].w * inv;
        whi[ob + j * 512 + t] = make_uint2(pack_h(__float2half_rn(w0), __float2half_rn(w1)),
                                           pack_h(__float2half_rn(w2), __float2half_rn(w3)));
    }
}

// ---------------- split-precision GEMM via mma.sync (templated) ----------------
// HAS_AL=true : C = (Ah+Al) . Bh^T  (2 products; GEMM1 logits)
// HAS_AL=false: C = Ah . Bh^T       (1 product;  GEMM2 retrieval)
// tile 128x128, BK=64, 2-stage cp.async pipeline, 256 threads, warp grid 4(M)x2(N),
// 2 CTAs per SM (cross-CTA overlap fills per-chunk sync/wait bubbles).
#define G_THREADS   256
#define TILE_BYTES  16384                   // 128 rows x 64 halfwords (128 B/row)

template <bool HAS_AL>
__global__ void __launch_bounds__(G_THREADS, 2)
gemm_split_kernel(const uint16_t* __restrict__ Ah, const uint16_t* __restrict__ Al,
                  const uint16_t* __restrict__ Bh,
                  float* __restrict__ C,
                  int M, int Ntot, int ldk, int Kloc, int group_m) {
    constexpr int NTILES = HAS_AL ? 3 : 2;
    constexpr int STAGE  = NTILES * TILE_BYTES;
    constexpr int NWM = 4, NWN = 2;
    constexpr int MI = 128 / NWM / 16;      // 2 m16 tiles per warp
    constexpr int NJ = 128 / NWN / 8;       // 8 n8 tiles per warp

    extern __shared__ char smem[];
    uint32_t sbase = smem_u32(smem);
    const int tid = threadIdx.x, lane = tid & 31, warp = tid >> 5;
    const int wm = warp % NWM, wn = warp / NWM;

    // supertile rasterization for L2 reuse
    int num_pid_m = M >> 7, num_pid_n = Ntot >> 7;
    int pid = blockIdx.x;
    int per_grp = group_m * num_pid_n;
    int gid = pid / per_grp;
    int first_m = gid * group_m;
    int gsm = num_pid_m - first_m; if (gsm > group_m) gsm = group_m;
    int pid_m = first_m + (pid % gsm);
    int pid_n = (pid % per_grp) / gsm;
    const int m0 = pid_m << 7, n0 = pid_n << 7;

    const int kbeg = blockIdx.y * Kloc;
    C += (size_t)blockIdx.y * M * Ntot;

    constexpr int B_SLOT = HAS_AL ? 2 : 1;

    auto stage_load = [&](int c, int buf) {
        size_t k0 = (size_t)kbeg + (size_t)c * 64;
        uint32_t sb = sbase + buf * STAGE;
        #pragma unroll
        for (int i = 0; i < 4; i++) {
            int idx = tid + i * G_THREADS;          // 0..1023
            int r = idx >> 3, cc = idx & 7;
            uint32_t off = (uint32_t)(r * 128 + (cc * 16 ^ ((r & 7) << 4)));
            cp16(sb + off, Ah + (size_t)(m0 + r) * ldk + k0 + cc * 8);
            if constexpr (HAS_AL)
                cp16(sb + TILE_BYTES + off, Al + (size_t)(m0 + r) * ldk + k0 + cc * 8);
            cp16(sb + B_SLOT * TILE_BYTES + off, Bh + (size_t)(n0 + r) * ldk + k0 + cc * 8);
        }
        cp_commit();
    };

    float acc[MI][NJ][4];
    #pragma unroll
    for (int i = 0; i < MI; i++)
        #pragma unroll
        for (int j = 0; j < NJ; j++)
            #pragma unroll
            for (int q = 0; q < 4; q++) acc[i][j][q] = 0.f;

    const int nch = Kloc >> 6;   // BK = 64
    stage_load(0, 0);

    // per-lane ldmatrix address components (row stride 128 B)
    const int rowA = wm * 32 + (lane & 7) + ((lane >> 3) & 1) * 8;    // + i*16
    const int kbA  = (lane >> 4) * 16;                                // bytes
    const uint32_t xorA = (uint32_t)((rowA & 7) << 4);
    const int rowB = wn * 64 + (lane & 7);                            // + j*8
    const int kbB  = ((lane >> 3) & 1) * 16;                          // bytes
    const uint32_t xorB = (uint32_t)((rowB & 7) << 4);

    for (int c = 0; c < nch; ++c) {
        if (c + 1 < nch) {
            stage_load(c + 1, (c + 1) & 1);
            cp_wait<1>();
        } else {
            cp_wait<0>();
        }
        __syncthreads();

        uint32_t sA  = sbase + (c & 1) * STAGE;
        uint32_t sAl = sA + TILE_BYTES;
        uint32_t sBh = sA + B_SLOT * TILE_BYTES;

        #pragma unroll
        for (int ks = 0; ks < 4; ks++) {
            uint32_t ah[MI][4], al[HAS_AL ? MI : 1][4], bh[NJ][2];
            #pragma unroll
            for (int i = 0; i < MI; i++) {
                uint32_t off = (uint32_t)((rowA + i * 16) * 128) + ((uint32_t)(ks * 32 + kbA) ^ xorA);
                ldsm_x4(ah[i], sA + off);
                if constexpr (HAS_AL) ldsm_x4(al[i], sAl + off);
            }
            #pragma unroll
            for (int j = 0; j < NJ; j++) {
                uint32_t off = (uint32_t)((rowB + j * 8) * 128) + ((uint32_t)(ks * 32 + kbB) ^ xorB);
                ldsm_x2(bh[j], sBh + off);
            }
            // product-major: main then (optional) correction
            #pragma unroll
            for (int i = 0; i < MI; i++)
                #pragma unroll
                for (int j = 0; j < NJ; j++)
                    mma_f32acc(acc[i][j], ah[i], bh[j]);
            if constexpr (HAS_AL) {
                #pragma unroll
                for (int i = 0; i < MI; i++)
                    #pragma unroll
                    for (int j = 0; j < NJ; j++)
                        mma_f32acc(acc[i][j], al[i], bh[j]);
            }
        }
        __syncthreads();
    }

    // epilogue: direct fp32 stores
    const int r0 = m0 + wm * 32 + (lane >> 2);
    const int c0 = n0 + wn * 64 + (lane & 3) * 2;
    #pragma unroll
    for (int i = 0; i < MI; i++) {
        #pragma unroll
        for (int j = 0; j < NJ; j++) {
            int r = r0 + i * 16, cc = c0 + j * 8;
            float2 v01 = make_float2(acc[i][j][0], acc[i][j][1]);
            float2 v23 = make_float2(acc[i][j][2], acc[i][j][3]);
            *reinterpret_cast<float2*>(&C[(size_t)r * Ntot + cc])       = v01;
            *reinterpret_cast<float2*>(&C[(size_t)(r + 8) * Ntot + cc]) = v23;
        }
    }
}

// ---------------- combine: out = x + alpha * sum_{s<4} R_s ----------------
__global__ void combine_kernel(const float4* __restrict__ x,
                               const float4* __restrict__ R,   // SPLITK contiguous partials
                               const float* __restrict__ alpha_p,
                               float4* __restrict__ out, int n4) {
    int i = blockIdx.x * blockDim.x + threadIdx.x;
    if (i >= n4) return;
    float al = *alpha_p;
    float4 xv = x[i];
    float sx = 0.f, sy = 0.f, sz = 0.f, sw = 0.f;
    #pragma unroll
    for (int s = 0; s < SPLITK; s++) {
        float4 r = R[(size_t)s * n4 + i];
        sx += r.x; sy += r.y; sz += r.z; sw += r.w;
    }
    float4 o;
    o.x = xv.x + al * sx;
    o.y = xv.y + al * sy;
    o.z = xv.z + al * sz;
    o.w = xv.w + al * sw;
    out[i] = o;
}

// ---------------- launch ----------------
extern "C" void kernel_launch(void* const* d_in, const int* in_sizes, int n_in,
                              void* d_out, int out_size) {
    const float* x     = (const float*)d_in[0];
    const float* ci    = (const float*)d_in[1];
    const float* ct    = (const float*)d_in[2];
    const float* beta  = (const float*)d_in[3];
    const float* alpha = (const float*)d_in[4];
    float* out = (float*)d_out;

    void *xh, *xl, *cih, *cth, *Sp, *wh, *Rp;
    cudaGetSymbolAddress(&xh,  g_x_hi);
    cudaGetSymbolAddress(&xl,  g_x_lo);
    cudaGetSymbolAddress(&cih, g_ci_hi);
    cudaGetSymbolAddress(&cth, g_ctT_hi);
    cudaGetSymbolAddress(&Sp,  g_S);
    cudaGetSymbolAddress(&wh,  g_w_hi);
    cudaGetSymbolAddress(&Rp,  g_R);

    auto gemm1 = gemm_split_kernel<true>;    // (Xh+Xl) . Ch
    auto gemm2 = gemm_split_kernel<false>;   // Wh . Vh
    const int SMEM1 = 2 * 3 * TILE_BYTES;    // 98304
    const int SMEM2 = 2 * 2 * TILE_BYTES;    // 65536
    cudaFuncSetAttribute(gemm1, cudaFuncAttributeMaxDynamicSharedMemorySize, SMEM1);
    cudaFuncSetAttribute(gemm2, cudaFuncAttributeMaxDynamicSharedMemorySize, SMEM2);

    // 1) split x to fp16 hi/lo; convert ci to fp16; transpose + fp16 convert ct
    {
        int n4 = DIM_B * DIM_D / 4;
        split_h_kernel<<<n4 / 256, 256>>>((const float4*)x, (uint2*)xh, (uint2*)xl, n4);
    }
    {
        int n4 = DIM_N * DIM_D / 4;
        cvt_h_kernel<<<n4 / 256, 256>>>((const float4*)ci, (uint2*)cih, n4);
    }
    transpose_h_kernel<<<dim3(DIM_D / 32, DIM_N / 32), dim3(32, 8)>>>(ct, (__half*)cth);

    // 2) logits S = x . ci^T   [4096 x 16384], K = 1024  (fp16, 2-product)
    gemm1<<<dim3((DIM_B / 128) * (DIM_N / 128), 1), G_THREADS, SMEM1>>>(
        (const uint16_t*)xh, (const uint16_t*)xl, (const uint16_t*)cih,
        (float*)Sp, DIM_B, DIM_N, DIM_D, DIM_D, 8);

    // 3) softmax(beta * S) row-wise -> fp16 weights (hi only)
    softmax_h_kernel<<<DIM_B, 512>>>((const float*)Sp, beta, (uint2*)wh);

    // 4) R_s = W . ctT^T over K-slice s  [4096 x 1024], K = 16384, split-K = 4
    //    (fp16, 1-product: Wh . Vh)
    gemm2<<<dim3((DIM_B / 128) * (DIM_D / 128), SPLITK), G_THREADS, SMEM2>>>(
        (const uint16_t*)wh, nullptr, (const uint16_t*)cth,
        (float*)Rp, DIM_B, DIM_D, DIM_N, DIM_N / SPLITK, 4);

    // 5) out = x + alpha * sum_s R_s
    {
        int n4 = DIM_B * DIM_D / 4;
        combine_kernel<<<n4 / 256, 256>>>(
            (const float4*)x, (const float4*)Rp, alpha, (float4*)out, n4);
    }
}